// round 1
// baseline (speedup 1.0000x reference)
#include <cuda_runtime.h>

#define LRELU_ALPHA 0.2f
#define NEGINF (-9.0e15f)

#define BATCH 8
#define NNODE 2048
#define FIN   256
#define FOUT  128

// Scratch (device globals: allocation-free per harness rules)
static __device__ float g_h[BATCH * NNODE * FOUT];    // 8.4 MB
static __device__ float g_f1[BATCH * NNODE];
static __device__ float g_f2[BATCH * NNODE];

// ---------- packed f32x2 helpers ----------
__device__ __forceinline__ unsigned long long pk2(float a, float b) {
    unsigned long long r;
    asm("mov.b64 %0, {%1,%2};" : "=l"(r) : "f"(a), "f"(b));
    return r;
}
__device__ __forceinline__ void upk2(unsigned long long v, float& a, float& b) {
    asm("mov.b64 {%0,%1}, %2;" : "=f"(a), "=f"(b) : "l"(v));
}
__device__ __forceinline__ unsigned long long ffma2(unsigned long long a,
                                                    unsigned long long b,
                                                    unsigned long long c) {
    unsigned long long d;
    asm("fma.rn.f32x2 %0, %1, %2, %3;" : "=l"(d) : "l"(a), "l"(b), "l"(c));
    return d;
}
__device__ __forceinline__ unsigned long long fmul2(unsigned long long a,
                                                    unsigned long long b) {
    unsigned long long d;
    asm("mul.rn.f32x2 %0, %1, %2;" : "=l"(d) : "l"(a), "l"(b));
    return d;
}

// ============================================================
// Kernel 1: h = x @ W ; f1 = h @ a1 ; f2 = h @ a2
// Block: 256 threads, 64 rows x 128 cols tile. Thread: 8 rows x 4 cols.
// ============================================================
__global__ void __launch_bounds__(256) k_gemm(const float* __restrict__ x,
                                              const float* __restrict__ W,
                                              const float* __restrict__ a) {
    __shared__ float xs[64][32];
    __shared__ float ws[32][128];
    const int t = threadIdx.x;
    const int row0 = blockIdx.x * 64;        // flattened b*N + n row base
    const int c4 = (t & 31) * 4;             // output col base (0..124)
    const int rg = t >> 5;                   // rowgroup == warp id (0..7)

    unsigned long long acc[8][2];
#pragma unroll
    for (int r = 0; r < 8; r++) { acc[r][0] = 0ULL; acc[r][1] = 0ULL; }

    for (int k0 = 0; k0 < FIN; k0 += 32) {
        // stage x tile (64 x 32)
        {
            const int rr = t >> 3;
            const int cc = (t & 7) * 4;
            float4 v0 = *reinterpret_cast<const float4*>(&x[(size_t)(row0 + rr) * FIN + k0 + cc]);
            float4 v1 = *reinterpret_cast<const float4*>(&x[(size_t)(row0 + rr + 32) * FIN + k0 + cc]);
            *reinterpret_cast<float4*>(&xs[rr][cc]) = v0;
            *reinterpret_cast<float4*>(&xs[rr + 32][cc]) = v1;
        }
        // stage W tile (32 x 128)
        {
            const int kr = t >> 5;
            const int cc = (t & 31) * 4;
#pragma unroll
            for (int i = 0; i < 4; i++) {
                float4 v = *reinterpret_cast<const float4*>(&W[(size_t)(k0 + kr + i * 8) * FOUT + cc]);
                *reinterpret_cast<float4*>(&ws[kr + i * 8][cc]) = v;
            }
        }
        __syncthreads();
#pragma unroll
        for (int k = 0; k < 32; k++) {
            ulonglong2 wv = *reinterpret_cast<const ulonglong2*>(&ws[k][c4]);
#pragma unroll
            for (int r = 0; r < 8; r++) {
                float xv = xs[rg * 8 + r][k];           // warp-broadcast read
                unsigned long long xd = pk2(xv, xv);
                acc[r][0] = ffma2(xd, wv.x, acc[r][0]);
                acc[r][1] = ffma2(xd, wv.y, acc[r][1]);
            }
        }
        __syncthreads();
    }

    // epilogue: write h, fused f1/f2 (warp owns one 8-row group, lanes span cols)
    float4 a1 = *reinterpret_cast<const float4*>(&a[c4]);
    float4 a2 = *reinterpret_cast<const float4*>(&a[FOUT + c4]);
#pragma unroll
    for (int r = 0; r < 8; r++) {
        float h0, h1, h2, h3;
        upk2(acc[r][0], h0, h1);
        upk2(acc[r][1], h2, h3);
        const int grow = row0 + rg * 8 + r;
        *reinterpret_cast<float4*>(&g_h[(size_t)grow * FOUT + c4]) = make_float4(h0, h1, h2, h3);
        float s1 = h0 * a1.x + h1 * a1.y + h2 * a1.z + h3 * a1.w;
        float s2 = h0 * a2.x + h1 * a2.y + h2 * a2.z + h3 * a2.w;
#pragma unroll
        for (int off = 16; off; off >>= 1) {
            s1 += __shfl_xor_sync(0xffffffffu, s1, off);
            s2 += __shfl_xor_sync(0xffffffffu, s2, off);
        }
        if ((t & 31) == 0) { g_f1[grow] = s1; g_f2[grow] = s2; }
    }
}

// ============================================================
// Kernel 2: fused masked-softmax attention + att @ h + ELU
// Block: 128 threads (4 warps), each warp owns 8 query rows.
// j processed in 32-wide tiles; h tile double-buffered via cp.async;
// adj prefetched one tile ahead in registers (the only HBM stream).
// ============================================================
#define JT 32
#define RW 8
#define NW 4

__global__ void __launch_bounds__(128, 4) k_attn(const int* __restrict__ adj,
                                                 float* __restrict__ out) {
    __shared__ float hs[2][JT][FOUT];          // 32 KB
    __shared__ float pd[NW][RW][JT][2];        // 8 KB, (p,p) duplicated pairs

    const int tid = threadIdx.x;
    const int w = tid >> 5, lane = tid & 31;
    const int b = blockIdx.y;
    const int row0 = blockIdx.x * (NW * RW);
    const int wrow0 = row0 + w * RW;
    const int* adjB = adj + (size_t)b * NNODE * NNODE;
    const float* hB = g_h + (size_t)b * NNODE * FOUT;

    float f1r[RW];
#pragma unroll
    for (int r = 0; r < RW; r++) f1r[r] = g_f1[b * NNODE + wrow0 + r];

    float m[RW], l[RW];
    unsigned long long acc[RW][2];
#pragma unroll
    for (int r = 0; r < RW; r++) { m[r] = NEGINF; l[r] = 0.f; acc[r][0] = 0ULL; acc[r][1] = 0ULL; }

    auto stage = [&](int tile) {
        const int buf = tile & 1;
        const float* src = hB + (size_t)tile * JT * FOUT;
#pragma unroll
        for (int k = 0; k < 8; k++) {
            int idx = tid + k * 128;                 // float4 index 0..1023
            int rr = idx >> 5, cc = (idx & 31) * 4;
            unsigned sm = (unsigned)__cvta_generic_to_shared(&hs[buf][rr][cc]);
            asm volatile("cp.async.cg.shared.global [%0], [%1], 16;"
                         :: "r"(sm), "l"(src + rr * FOUT + cc));
        }
        asm volatile("cp.async.commit_group;");
    };

    stage(0);

    // prefetch adj + f2 for tile 0
    int aCur[RW];
    float f2Cur;
    {
        const int j = lane;
#pragma unroll
        for (int r = 0; r < RW; r++) aCur[r] = adjB[(size_t)(wrow0 + r) * NNODE + j];
        f2Cur = g_f2[b * NNODE + j];
    }

    const int NT = NNODE / JT;   // 64
    for (int t = 0; t < NT; t++) {
        if (t + 1 < NT) {
            stage(t + 1);
            asm volatile("cp.async.wait_group 1;");
        } else {
            asm volatile("cp.async.wait_group 0;");
        }
        __syncthreads();

        // prefetch next adj tile (hides HBM latency under FFMA work)
        int aNext[RW];
        float f2Next = 0.f;
        if (t + 1 < NT) {
            const int j = (t + 1) * JT + lane;
#pragma unroll
            for (int r = 0; r < RW; r++) aNext[r] = adjB[(size_t)(wrow0 + r) * NNODE + j];
            f2Next = g_f2[b * NNODE + j];
        }

        // online softmax for this 32-wide chunk (lane <-> j)
#pragma unroll
        for (int r = 0; r < RW; r++) {
            float tt = f1r[r] + f2Cur;
            float e = tt > 0.f ? tt : LRELU_ALPHA * tt;
            e = (aCur[r] > 0) ? e : NEGINF;
            float cm = e;
#pragma unroll
            for (int off = 16; off; off >>= 1)
                cm = fmaxf(cm, __shfl_xor_sync(0xffffffffu, cm, off));
            float mn = fmaxf(m[r], cm);
            float sc = __expf(m[r] - mn);
            float pv = __expf(e - mn);
            float sp = pv;
#pragma unroll
            for (int off = 16; off; off >>= 1)
                sp += __shfl_xor_sync(0xffffffffu, sp, off);
            l[r] = l[r] * sc + sp;
            m[r] = mn;
            unsigned long long s2 = pk2(sc, sc);
            acc[r][0] = fmul2(acc[r][0], s2);
            acc[r][1] = fmul2(acc[r][1], s2);
            *reinterpret_cast<unsigned long long*>(&pd[w][r][lane][0]) = pk2(pv, pv);
        }
        __syncwarp();

        // acc += p * h : pure FFMA2 inner loop (binding pipe)
        const int buf = t & 1;
#pragma unroll 4
        for (int jj = 0; jj < JT; jj++) {
            ulonglong2 hv = *reinterpret_cast<const ulonglong2*>(&hs[buf][jj][lane * 4]);
#pragma unroll
            for (int r = 0; r < RW; r++) {
                unsigned long long pr =
                    *reinterpret_cast<const unsigned long long*>(&pd[w][r][jj][0]);
                acc[r][0] = ffma2(pr, hv.x, acc[r][0]);
                acc[r][1] = ffma2(pr, hv.y, acc[r][1]);
            }
        }
        __syncthreads();
#pragma unroll
        for (int r = 0; r < RW; r++) aCur[r] = aNext[r];
        f2Cur = f2Next;
    }

    // epilogue: normalize, ELU, store
#pragma unroll
    for (int r = 0; r < RW; r++) {
        float inv = 1.0f / l[r];
        float v0, v1, v2, v3;
        upk2(acc[r][0], v0, v1);
        upk2(acc[r][1], v2, v3);
        v0 *= inv; v1 *= inv; v2 *= inv; v3 *= inv;
        v0 = v0 > 0.f ? v0 : expm1f(v0);
        v1 = v1 > 0.f ? v1 : expm1f(v1);
        v2 = v2 > 0.f ? v2 : expm1f(v2);
        v3 = v3 > 0.f ? v3 : expm1f(v3);
        *reinterpret_cast<float4*>(
            &out[(size_t)(b * NNODE + wrow0 + r) * FOUT + lane * 4]) =
            make_float4(v0, v1, v2, v3);
    }
}

// ============================================================
extern "C" void kernel_launch(void* const* d_in, const int* in_sizes, int n_in,
                              void* d_out, int out_size) {
    const float* x   = (const float*)d_in[0];   // (8, 2048, 256) f32
    const int*   adj = (const int*)d_in[1];     // (8, 2048, 2048) i32
    const float* W   = (const float*)d_in[2];   // (256, 128) f32
    const float* a   = (const float*)d_in[3];   // (256, 1) f32
    float* out = (float*)d_out;                 // (8, 2048, 128) f32

    k_gemm<<<(BATCH * NNODE) / 64, 256>>>(x, W, a);
    dim3 grid(NNODE / (NW * RW), BATCH);
    k_attn<<<grid, 128>>>(adj, out);
}